// round 3
// baseline (speedup 1.0000x reference)
#include <cuda_runtime.h>
#include <cuda_bf16.h>

#define NSITES 500000
#define C1 128
#define CH 64
#define C2 128
#define EPS 1e-5f

// h = silu(bn1(features @ W1)), [N, 64]
__device__ float g_h[NSITES * CH];

// ---------- packed f32x2 helpers ----------
__device__ __forceinline__ void fma2(unsigned long long& d, unsigned long long a, unsigned long long b) {
    asm("fma.rn.f32x2 %0, %1, %2, %0;" : "+l"(d) : "l"(a), "l"(b));
}
__device__ __forceinline__ unsigned long long pk2(float x) {
    unsigned long long r;
    asm("mov.b64 %0, {%1, %1};" : "=l"(r) : "f"(x));
    return r;
}
__device__ __forceinline__ float2 up2(unsigned long long v) {
    float2 r;
    asm("mov.b64 {%0, %1}, %2;" : "=f"(r.x), "=f"(r.y) : "l"(v));
    return r;
}
__device__ __forceinline__ float silu_f(float x) {
    return x / (1.0f + __expf(-x));
}

// ============================================================================
// Kernel 1: h = silu(bn1(features @ W1))   [N,128] x [128,64] -> [N,64]
// 128 sites per block, 256 threads. cg = t&7 (8 col groups x 8 ch),
// rg = t>>3 (32 row groups). Thread handles rows {rg, rg+32, rg+64, rg+96}
// (stride-32 assignment -> conflict-free smem reads) x 8 channels.
// ============================================================================
#define K1_STRIDE 132

__global__ __launch_bounds__(256, 2) void k1_cv1(
    const float* __restrict__ feat,
    const float* __restrict__ W1,
    const float* __restrict__ g1, const float* __restrict__ b1,
    const float* __restrict__ m1, const float* __restrict__ v1)
{
    extern __shared__ float sm[];
    float* sW = sm;                 // 128*64 = 8192 floats
    float* sF = sm + 8192;          // 128 * 132 floats

    int t = threadIdx.x;
    int base = blockIdx.x * 128;

    // Load W1 (8192 floats = 2048 float4)
    {
        const float4* w4 = (const float4*)W1;
        float4* sw4 = (float4*)sW;
        #pragma unroll
        for (int i = 0; i < 8; i++) sw4[t + 256 * i] = w4[t + 256 * i];
    }
    // Load feature tile: 128 rows x 128 floats (float4 granules)
    for (int q = t; q < 128 * 32; q += 256) {
        int r = q >> 5, c4 = q & 31;
        int site = base + r;
        float4 v = make_float4(0.f, 0.f, 0.f, 0.f);
        if (site < NSITES) v = ((const float4*)feat)[site * 32 + c4];
        float* dst = sF + r * K1_STRIDE + c4 * 4;
        dst[0] = v.x; dst[1] = v.y; dst[2] = v.z; dst[3] = v.w;
    }
    __syncthreads();

    int cg = t & 7;
    int rg = t >> 3;

    unsigned long long acc[4][4];
    #pragma unroll
    for (int i = 0; i < 4; i++)
        #pragma unroll
        for (int p = 0; p < 4; p++) acc[i][p] = 0ull;

    #pragma unroll 2
    for (int j4 = 0; j4 < 128; j4 += 4) {
        float4 a[4];
        #pragma unroll
        for (int i = 0; i < 4; i++)
            a[i] = *(const float4*)(sF + (rg + 32 * i) * K1_STRIDE + j4);
        #pragma unroll
        for (int u = 0; u < 4; u++) {
            const unsigned long long* wp =
                (const unsigned long long*)(sW + (j4 + u) * 64 + cg * 8);
            unsigned long long w0 = wp[0], w1 = wp[1], w2 = wp[2], w3 = wp[3];
            #pragma unroll
            for (int i = 0; i < 4; i++) {
                float av = (u == 0) ? a[i].x : (u == 1) ? a[i].y : (u == 2) ? a[i].z : a[i].w;
                unsigned long long p = pk2(av);
                fma2(acc[i][0], p, w0); fma2(acc[i][1], p, w1);
                fma2(acc[i][2], p, w2); fma2(acc[i][3], p, w3);
            }
        }
    }

    // BN1 + SiLU epilogue
    float sc[8], tb[8];
    #pragma unroll
    for (int c = 0; c < 8; c++) {
        int ch = cg * 8 + c;
        float s = g1[ch] * rsqrtf(v1[ch] + EPS);
        sc[c] = s;
        tb[c] = b1[ch] - m1[ch] * s;
    }
    #pragma unroll
    for (int i = 0; i < 4; i++) {
        int site = base + rg + 32 * i;
        if (site < NSITES) {
            float o[8];
            #pragma unroll
            for (int p = 0; p < 4; p++) {
                float2 v = up2(acc[i][p]);
                o[2 * p] = v.x; o[2 * p + 1] = v.y;
            }
            #pragma unroll
            for (int c = 0; c < 8; c++)
                o[c] = silu_f(o[c] * sc[c] + tb[c]);
            float4* dst = (float4*)(g_h + site * CH + cg * 8);
            dst[0] = make_float4(o[0], o[1], o[2], o[3]);
            dst[1] = make_float4(o[4], o[5], o[6], o[7]);
        }
    }
}

// ============================================================================
// Kernel 2: fused cv2 (sparse 3x3 rulebook conv) + BN2/SiLU + cv3 + BN3 +
// residual + SiLU.  128 sites per block, 256 threads.
// cv2 matmul: 4 rows x 8 cols per thread (rows 4*rg+i over compacted list).
// ============================================================================
#define GAT_STRIDE 68
#define ACC_STRIDE 68

__global__ __launch_bounds__(256, 2) void k2_cv23(
    const float* __restrict__ feat,
    const int* __restrict__ nbr,
    const float* __restrict__ W2,
    const float* __restrict__ W3,
    const float* __restrict__ g2, const float* __restrict__ b2,
    const float* __restrict__ m2, const float* __restrict__ v2,
    const float* __restrict__ g3, const float* __restrict__ b3,
    const float* __restrict__ m3, const float* __restrict__ v3,
    float* __restrict__ out)
{
    extern __shared__ float sm[];
    float* sAcc = sm;                   // 128 * 68 = 8704 floats
    float* sGat = sm + 8704;            // 128 * 68 = 8704 floats
    float* sW   = sm + 17408;           // 8192 floats (W2[k] / later W3)
    int* lrow = (int*)(sm + 25600);     // 128
    int* lgat = lrow + 128;             // 128
    int* pcnt = lgat + 128;             // 1

    int t = threadIdx.x;
    int lane = t & 31;
    int base = blockIdx.x * 128;

    // zero accumulator
    for (int q = t; q < 128 * ACC_STRIDE; q += 256) sAcc[q] = 0.f;

    int cg = t & 7;        // 8-channel group for cv2
    int rg = t >> 3;       // row group: rows 4*rg .. 4*rg+3

    if (t == 0) *pcnt = 0;
    __syncthreads();

    for (int k = 0; k < 9; k++) {
        // compact valid neighbors via warp ballot (threads 0..127 = 4 full warps)
        if (t < 128) {
            int site = base + t;
            int id = NSITES;
            if (site < NSITES) id = nbr[k * NSITES + site];
            bool valid = (id < NSITES);
            unsigned mask = __ballot_sync(0xffffffffu, valid);
            int cnt = __popc(mask);
            int wbase = 0;
            if (lane == 0 && cnt) wbase = atomicAdd(pcnt, cnt);
            wbase = __shfl_sync(0xffffffffu, wbase, 0);
            if (valid) {
                int pos = wbase + __popc(mask & ((1u << lane) - 1u));
                lrow[pos] = t;
                lgat[pos] = id;
            }
        }
        // load W2[k] (4096 floats = 1024 float4)
        {
            const float4* w4 = (const float4*)(W2 + k * (CH * CH));
            float4* sw4 = (float4*)sW;
            #pragma unroll
            for (int i = 0; i < 4; i++) sw4[t + 256 * i] = w4[t + 256 * i];
        }
        __syncthreads();
        int m = *pcnt;

        // gather h rows of valid neighbors (float4 granules)
        for (int q = t; q < m * 16; q += 256) {
            int r = q >> 4, c4 = q & 15;
            float4 v = ((const float4*)g_h)[lgat[r] * 16 + c4];
            float* dst = sGat + r * GAT_STRIDE + c4 * 4;
            dst[0] = v.x; dst[1] = v.y; dst[2] = v.z; dst[3] = v.w;
        }
        __syncthreads();

        // compacted matmul: rows 4*rg+i, only warps with rows < m are busy
        if (4 * rg < m) {
            int rr[4];
            #pragma unroll
            for (int i = 0; i < 4; i++) {
                int r = 4 * rg + i;
                rr[i] = (r < m) ? r : (m - 1);
            }
            unsigned long long acc[4][4];
            #pragma unroll
            for (int i = 0; i < 4; i++)
                #pragma unroll
                for (int p = 0; p < 4; p++) acc[i][p] = 0ull;

            #pragma unroll 2
            for (int j4 = 0; j4 < 64; j4 += 4) {
                float4 a[4];
                #pragma unroll
                for (int i = 0; i < 4; i++)
                    a[i] = *(const float4*)(sGat + rr[i] * GAT_STRIDE + j4);
                #pragma unroll
                for (int u = 0; u < 4; u++) {
                    const unsigned long long* wp =
                        (const unsigned long long*)(sW + (j4 + u) * 64 + cg * 8);
                    unsigned long long w0 = wp[0], w1 = wp[1], w2 = wp[2], w3 = wp[3];
                    #pragma unroll
                    for (int i = 0; i < 4; i++) {
                        float av = (u == 0) ? a[i].x : (u == 1) ? a[i].y : (u == 2) ? a[i].z : a[i].w;
                        unsigned long long p = pk2(av);
                        fma2(acc[i][0], p, w0); fma2(acc[i][1], p, w1);
                        fma2(acc[i][2], p, w2); fma2(acc[i][3], p, w3);
                    }
                }
            }
            #pragma unroll
            for (int i = 0; i < 4; i++) {
                if (4 * rg + i < m) {
                    float* ap = sAcc + lrow[rr[i]] * ACC_STRIDE + cg * 8;
                    #pragma unroll
                    for (int p = 0; p < 4; p++) {
                        float2 v = up2(acc[i][p]);
                        ap[2 * p]     += v.x;
                        ap[2 * p + 1] += v.y;
                    }
                }
            }
        }
        if (t == 0) *pcnt = 0;   // reset for next k (pcnt already consumed)
        __syncthreads();
    }

    // BN2 + SiLU in place on sAcc
    for (int q = t; q < 128 * 64; q += 256) {
        int s = q >> 6, c = q & 63;
        float sc2 = g2[c] * rsqrtf(v2[c] + EPS);
        float tb2 = b2[c] - m2[c] * sc2;
        float x = sAcc[s * ACC_STRIDE + c] * sc2 + tb2;
        sAcc[s * ACC_STRIDE + c] = silu_f(x);
    }
    __syncthreads();

    // load W3 (64x128 = 8192 floats)
    {
        const float4* w4 = (const float4*)W3;
        float4* sw4 = (float4*)sW;
        #pragma unroll
        for (int i = 0; i < 8; i++) sw4[t + 256 * i] = w4[t + 256 * i];
    }
    __syncthreads();

    // cv3: [128,64] @ [64,128]; thread = (sgrp = t>>4 -> 4 sites, cg16 = t&15 -> 8 ch)
    int cg16 = t & 15;
    int c0 = cg16 * 8;
    int sgrp = t >> 4;

    float sc3[8], tb3[8];
    #pragma unroll
    for (int c = 0; c < 8; c++) {
        int ch = c0 + c;
        float s = g3[ch] * rsqrtf(v3[ch] + EPS);
        sc3[c] = s;
        tb3[c] = b3[ch] - m3[ch] * s;
    }

    for (int pass = 0; pass < 2; pass++) {
        int sbase = pass * 64 + sgrp * 4;
        unsigned long long acc[4][4];
        #pragma unroll
        for (int i = 0; i < 4; i++)
            #pragma unroll
            for (int p = 0; p < 4; p++) acc[i][p] = 0ull;

        #pragma unroll 2
        for (int j4 = 0; j4 < 64; j4 += 4) {
            float4 a[4];
            #pragma unroll
            for (int i = 0; i < 4; i++)
                a[i] = *(const float4*)(sAcc + (sbase + i) * ACC_STRIDE + j4);
            #pragma unroll
            for (int u = 0; u < 4; u++) {
                const unsigned long long* wp =
                    (const unsigned long long*)(sW + (j4 + u) * 128 + c0);
                unsigned long long w0 = wp[0], w1 = wp[1], w2 = wp[2], w3v = wp[3];
                #pragma unroll
                for (int i = 0; i < 4; i++) {
                    float av = (u == 0) ? a[i].x : (u == 1) ? a[i].y : (u == 2) ? a[i].z : a[i].w;
                    unsigned long long p = pk2(av);
                    fma2(acc[i][0], p, w0); fma2(acc[i][1], p, w1);
                    fma2(acc[i][2], p, w2); fma2(acc[i][3], p, w3v);
                }
            }
        }

        #pragma unroll
        for (int i = 0; i < 4; i++) {
            int site = base + sbase + i;
            if (site < NSITES) {
                float o[8];
                #pragma unroll
                for (int p = 0; p < 4; p++) {
                    float2 v = up2(acc[i][p]);
                    o[2 * p] = v.x; o[2 * p + 1] = v.y;
                }
                const float4* fr = (const float4*)(feat + site * C2 + c0);
                float4 fA = fr[0], fB = fr[1];
                float fv[8] = {fA.x, fA.y, fA.z, fA.w, fB.x, fB.y, fB.z, fB.w};
                #pragma unroll
                for (int c = 0; c < 8; c++)
                    o[c] = silu_f(o[c] * sc3[c] + tb3[c] + fv[c]);
                float4* dst = (float4*)(out + site * C2 + c0);
                dst[0] = make_float4(o[0], o[1], o[2], o[3]);
                dst[1] = make_float4(o[4], o[5], o[6], o[7]);
            }
        }
    }
}

// ============================================================================
// launch
// ============================================================================
extern "C" void kernel_launch(void* const* d_in, const int* in_sizes, int n_in,
                              void* d_out, int out_size) {
    const float* feat = (const float*)d_in[0];
    const int*   nbr  = (const int*)d_in[1];
    const float* W1   = (const float*)d_in[2];
    const float* W2   = (const float*)d_in[3];
    const float* W3   = (const float*)d_in[4];
    const float* g1 = (const float*)d_in[5];
    const float* b1 = (const float*)d_in[6];
    const float* m1 = (const float*)d_in[7];
    const float* v1 = (const float*)d_in[8];
    const float* g2 = (const float*)d_in[9];
    const float* b2 = (const float*)d_in[10];
    const float* m2 = (const float*)d_in[11];
    const float* v2 = (const float*)d_in[12];
    const float* g3 = (const float*)d_in[13];
    const float* b3 = (const float*)d_in[14];
    const float* m3 = (const float*)d_in[15];
    const float* v3 = (const float*)d_in[16];
    float* out = (float*)d_out;

    const int smem1 = (8192 + 128 * K1_STRIDE) * 4;                     // 100352
    const int smem2 = (128 * ACC_STRIDE + 128 * GAT_STRIDE + 8192) * 4
                      + 257 * 4 + 4;                                    // ~103.5 KB
    cudaFuncSetAttribute(k1_cv1, cudaFuncAttributeMaxDynamicSharedMemorySize, smem1);
    cudaFuncSetAttribute(k2_cv23, cudaFuncAttributeMaxDynamicSharedMemorySize, smem2);

    int grid = (NSITES + 127) / 128;    // 3907

    k1_cv1<<<grid, 256, smem1>>>(feat, W1, g1, b1, m1, v1);
    k2_cv23<<<grid, 256, smem2>>>(feat, nbr, W2, W3,
                                  g2, b2, m2, v2, g3, b3, m3, v3, out);
}

// round 6
// speedup vs baseline: 1.1217x; 1.1217x over previous
#include <cuda_runtime.h>
#include <cuda_bf16.h>
#include <cstdint>

#define NS 500000
#define EPS 1e-5f

// split-bf16 hidden activations: 2 channels packed per u32, 32 u32 per site
__device__ __align__(16) unsigned g_hhi[NS * 32];
__device__ __align__(16) unsigned g_hlo[NS * 32];
// padded ldmatrix-ready weight images: [K][N+pad] u16, built by k0
__device__ __align__(16) unsigned short gW1hi[128 * 72], gW1lo[128 * 72];
__device__ __align__(16) unsigned short gW2hi[9 * 64 * 72], gW2lo[9 * 64 * 72];
__device__ __align__(16) unsigned short gW3hi[64 * 136], gW3lo[64 * 136];

__device__ __forceinline__ uint32_t s2u(const void* p) {
    uint32_t a;
    asm("{ .reg .u64 t; cvta.to.shared.u64 t, %1; cvt.u32.u64 %0, t; }" : "=r"(a) : "l"(p));
    return a;
}
__device__ __forceinline__ float silu(float x) { return x / (1.0f + __expf(-x)); }
__device__ __forceinline__ unsigned pack2(__nv_bfloat16 a, __nv_bfloat16 b) {
    return (unsigned)__bfloat16_as_ushort(a) | ((unsigned)__bfloat16_as_ushort(b) << 16);
}
__device__ __forceinline__ void ldmA(unsigned r[4], uint32_t a) {
    asm volatile("ldmatrix.sync.aligned.m8n8.x4.shared.b16 {%0,%1,%2,%3}, [%4];"
                 : "=r"(r[0]), "=r"(r[1]), "=r"(r[2]), "=r"(r[3]) : "r"(a));
}
__device__ __forceinline__ void ldmB(unsigned r[2], uint32_t a) {
    asm volatile("ldmatrix.sync.aligned.m8n8.x2.trans.shared.b16 {%0,%1}, [%2];"
                 : "=r"(r[0]), "=r"(r[1]) : "r"(a));
}
__device__ __forceinline__ void mmab(float d[4], const unsigned a[4], const unsigned b[2]) {
    asm volatile(
        "mma.sync.aligned.m16n8k16.row.col.f32.bf16.bf16.f32 "
        "{%0,%1,%2,%3},{%4,%5,%6,%7},{%8,%9},{%0,%1,%2,%3};"
        : "+f"(d[0]), "+f"(d[1]), "+f"(d[2]), "+f"(d[3])
        : "r"(a[0]), "r"(a[1]), "r"(a[2]), "r"(a[3]), "r"(b[0]), "r"(b[1]));
}

// ============================================================================
// k0: transpose + hi/lo-split + pad weights into ldmatrix B images [K][N+pad]
// ============================================================================
__global__ void k0(const float* __restrict__ W1, const float* __restrict__ W2,
                   const float* __restrict__ W3) {
    int i = blockIdx.x * 256 + threadIdx.x;
    float x;
    unsigned short *dh, *dl;
    int idx;
    if (i < 9216) {                       // W1: [128k][64n] -> [128][72]
        int k = i / 72, n = i % 72;
        x = (n < 64) ? W1[k * 64 + n] : 0.f;
        idx = i; dh = gW1hi; dl = gW1lo;
    } else if (i < 50688) {               // W2[kk]: [64k][64n] -> [9][64][72]
        int j = i - 9216;
        int kk = j / 4608, r = j % 4608, ki = r / 72, n = r % 72;
        x = (n < 64) ? W2[kk * 4096 + ki * 64 + n] : 0.f;
        idx = j; dh = gW2hi; dl = gW2lo;
    } else if (i < 59392) {               // W3: [64k][128n] -> [64][136]
        int j = i - 50688;
        int ki = j / 136, n = j % 136;
        x = (n < 128) ? W3[ki * 128 + n] : 0.f;
        idx = j; dh = gW3hi; dl = gW3lo;
    } else return;
    __nv_bfloat16 h = __float2bfloat16(x);
    dh[idx] = __bfloat16_as_ushort(h);
    dl[idx] = __bfloat16_as_ushort(__float2bfloat16(x - __bfloat162float(h)));
}

// ============================================================================
// k1: h = silu(bn1(feat @ W1))  [128 rows/block, 128 thr, warp = 32 rows]
// ============================================================================
#define O_B1HI 0
#define O_B1LO 18432
#define O_A1HI 36864
#define O_A1LO 47104
#define O_P1SC 57344
#define O_P1TB 57600
#define SM1    57856

__global__ __launch_bounds__(128) void k1(
    const float* __restrict__ feat,
    const float* __restrict__ g1, const float* __restrict__ b1,
    const float* __restrict__ m1, const float* __restrict__ v1)
{
    extern __shared__ char sm[];
    uint32_t sb = s2u(sm);
    int t = threadIdx.x, wid = t >> 5, lane = t & 31;
    int base = blockIdx.x * 128;

    {   // W1 images: 4608 u32 each  (FIX: was 18 iters = half the image)
        const unsigned* sh = (const unsigned*)gW1hi;
        const unsigned* sl = (const unsigned*)gW1lo;
        unsigned* dh = (unsigned*)(sm + O_B1HI);
        unsigned* dl = (unsigned*)(sm + O_B1LO);
        #pragma unroll
        for (int i = 0; i < 36; i++) { dh[t + 128 * i] = sh[t + 128 * i]; dl[t + 128 * i] = sl[t + 128 * i]; }
    }
    if (t < 64) {
        float s = g1[t] * rsqrtf(v1[t] + EPS);
        ((float*)(sm + O_P1SC))[t] = s;
        ((float*)(sm + O_P1TB))[t] = b1[t] - m1[t] * s;
    }

    float d[2][8][4] = {};
    int arow = ((lane >> 3) & 1) * 8 + (lane & 7);
    int acol = (lane >> 4) * 16;
    int brow = arow;

    for (int kc = 0; kc < 4; kc++) {
        __syncthreads();
        // stage A chunk (K=32) split bf16, row stride 80B
        #pragma unroll
        for (int i = 0; i < 16; i++) {
            int idx = t + 128 * i, r = idx >> 4, p = idx & 15;
            int site = base + r;
            float2 f = (site < NS) ? ((const float2*)feat)[(size_t)site * 64 + kc * 16 + p]
                                   : make_float2(0.f, 0.f);
            __nv_bfloat16 h0 = __float2bfloat16(f.x), h1 = __float2bfloat16(f.y);
            *(unsigned*)(sm + O_A1HI + r * 80 + p * 4) = pack2(h0, h1);
            *(unsigned*)(sm + O_A1LO + r * 80 + p * 4) =
                pack2(__float2bfloat16(f.x - __bfloat162float(h0)),
                      __float2bfloat16(f.y - __bfloat162float(h1)));
        }
        __syncthreads();
        unsigned ah[2][2][4], al[2][2][4], bhf[8][2][2], blf[8][2][2];
        #pragma unroll
        for (int mt = 0; mt < 2; mt++)
            #pragma unroll
            for (int kq = 0; kq < 2; kq++) {
                uint32_t a = sb + O_A1HI + (wid * 32 + mt * 16 + arow) * 80 + kq * 32 + acol;
                ldmA(ah[mt][kq], a);
                ldmA(al[mt][kq], a + (O_A1LO - O_A1HI));
            }
        #pragma unroll
        for (int n8 = 0; n8 < 8; n8++)
            #pragma unroll
            for (int kq = 0; kq < 2; kq++) {
                uint32_t a = sb + O_B1HI + (kc * 32 + kq * 16 + brow) * 144 + n8 * 16;
                ldmB(bhf[n8][kq], a);
                ldmB(blf[n8][kq], a + (O_B1LO - O_B1HI));
            }
        #pragma unroll
        for (int mt = 0; mt < 2; mt++)
            #pragma unroll
            for (int n8 = 0; n8 < 8; n8++)
                #pragma unroll
                for (int kq = 0; kq < 2; kq++) {
                    mmab(d[mt][n8], ah[mt][kq], bhf[n8][kq]);
                    mmab(d[mt][n8], ah[mt][kq], blf[n8][kq]);
                    mmab(d[mt][n8], al[mt][kq], bhf[n8][kq]);
                }
    }
    // BN1 + SiLU + split, direct global store
    const float* sc = (const float*)(sm + O_P1SC);
    const float* tb = (const float*)(sm + O_P1TB);
    #pragma unroll
    for (int mt = 0; mt < 2; mt++)
        #pragma unroll
        for (int n8 = 0; n8 < 8; n8++) {
            int c = 8 * n8 + 2 * (lane & 3);
            float s0 = sc[c], s1 = sc[c + 1], t0 = tb[c], t1 = tb[c + 1];
            #pragma unroll
            for (int h = 0; h < 2; h++) {
                int site = base + wid * 32 + mt * 16 + (lane >> 2) + 8 * h;
                if (site < NS) {
                    float o0 = silu(d[mt][n8][2 * h] * s0 + t0);
                    float o1 = silu(d[mt][n8][2 * h + 1] * s1 + t1);
                    __nv_bfloat16 x0 = __float2bfloat16(o0), x1 = __float2bfloat16(o1);
                    g_hhi[(size_t)site * 32 + (c >> 1)] = pack2(x0, x1);
                    g_hlo[(size_t)site * 32 + (c >> 1)] =
                        pack2(__float2bfloat16(o0 - __bfloat162float(x0)),
                              __float2bfloat16(o1 - __bfloat162float(x1)));
                }
            }
        }
}

// ============================================================================
// k2: cv2 (compacted rulebook conv, smem f32 scatter-accum) + BN2/SiLU +
//     cv3 (+BN3+residual+SiLU)
// ============================================================================
#define O_ACC  0          // f32 [128][72]
#define O_GHI  36864      // u16 [128][72] gather / A3 tile
#define O_GLO  55296
#define O_WHI  73728      // u16 [64][72]  W2[k]
#define O_WLO  82944
#define O_LROW 92160
#define O_LGAT 92672
#define O_CNT  93184
#define O_SC2  93200
#define O_TB2  93456
#define O_SC3  93712
#define O_TB3  94224
#define SM2    94736
#define O_W3HI 0          // reuse ACC region: u16 [64][136]
#define O_W3LO 17408

__global__ __launch_bounds__(128) void k2(
    const float* __restrict__ feat, const int* __restrict__ nbr,
    const float* __restrict__ g2, const float* __restrict__ b2,
    const float* __restrict__ m2, const float* __restrict__ v2,
    const float* __restrict__ g3, const float* __restrict__ b3,
    const float* __restrict__ m3, const float* __restrict__ v3,
    float* __restrict__ out)
{
    extern __shared__ char sm[];
    uint32_t sb = s2u(sm);
    int t = threadIdx.x, wid = t >> 5, lane = t & 31;
    int base = blockIdx.x * 128;
    int* lrow = (int*)(sm + O_LROW);
    int* lgat = (int*)(sm + O_LGAT);
    int* cnt = (int*)(sm + O_CNT);
    float* acc = (float*)(sm + O_ACC);

    if (t < 64) {
        float s = g2[t] * rsqrtf(v2[t] + EPS);
        ((float*)(sm + O_SC2))[t] = s;
        ((float*)(sm + O_TB2))[t] = b2[t] - m2[t] * s;
    }
    {
        float s = g3[t] * rsqrtf(v3[t] + EPS);
        ((float*)(sm + O_SC3))[t] = s;
        ((float*)(sm + O_TB3))[t] = b3[t] - m3[t] * s;
    }
    for (int i = 0; i < 72; i++) acc[t + 128 * i] = 0.f;
    if (t == 0) *cnt = 0;

    int arow = ((lane >> 3) & 1) * 8 + (lane & 7);
    int acol = (lane >> 4) * 16;
    int brow = arow;

    for (int k = 0; k < 9; k++) {
        __syncthreads();
        {   // W2[k] image copy (2304 u32 — correct for 64x72)
            const unsigned* sh = (const unsigned*)(gW2hi + k * 4608);
            const unsigned* sl = (const unsigned*)(gW2lo + k * 4608);
            unsigned* dh = (unsigned*)(sm + O_WHI);
            unsigned* dl = (unsigned*)(sm + O_WLO);
            #pragma unroll
            for (int i = 0; i < 18; i++) { dh[t + 128 * i] = sh[t + 128 * i]; dl[t + 128 * i] = sl[t + 128 * i]; }
        }
        {   // compact valid neighbors
            int site = base + t;
            int id = (site < NS) ? __ldg(&nbr[(size_t)k * NS + site]) : NS;
            bool val = id < NS;
            unsigned msk = __ballot_sync(0xffffffffu, val);
            int wb = 0;
            if (lane == 0 && msk) wb = atomicAdd(cnt, __popc(msk));
            wb = __shfl_sync(0xffffffffu, wb, 0);
            if (val) {
                int p = wb + __popc(msk & ((1u << lane) - 1u));
                lrow[p] = t; lgat[p] = id;
            }
        }
        __syncthreads();
        int m = *cnt;
        for (int q = t; q < m * 32; q += 128) {   // gather split-bf16 rows
            int r = q >> 5, w = q & 31;
            int id = lgat[r];
            *(unsigned*)(sm + O_GHI + r * 144 + w * 4) = g_hhi[(size_t)id * 32 + w];
            *(unsigned*)(sm + O_GLO + r * 144 + w * 4) = g_hlo[(size_t)id * 32 + w];
        }
        if (t == 0) *cnt = 0;
        __syncthreads();
        int mtiles = (m + 15) >> 4;
        unsigned bhf[2][4][2], blf[2][4][2];
        #pragma unroll
        for (int j = 0; j < 2; j++)
            #pragma unroll
            for (int kq = 0; kq < 4; kq++) {
                uint32_t a = sb + O_WHI + (kq * 16 + brow) * 144 + wid * 32 + j * 16;
                ldmB(bhf[j][kq], a);
                ldmB(blf[j][kq], a + (O_WLO - O_WHI));
            }
        for (int mt = 0; mt < mtiles; mt++) {
            unsigned ah[4][4], al[4][4];
            #pragma unroll
            for (int kq = 0; kq < 4; kq++) {
                uint32_t a = sb + O_GHI + (mt * 16 + arow) * 144 + kq * 32 + acol;
                ldmA(ah[kq], a);
                ldmA(al[kq], a + (O_GLO - O_GHI));
            }
            float dd[2][4] = {};
            #pragma unroll
            for (int j = 0; j < 2; j++)
                #pragma unroll
                for (int kq = 0; kq < 4; kq++) {
                    mmab(dd[j], ah[kq], bhf[j][kq]);
                    mmab(dd[j], ah[kq], blf[j][kq]);
                    mmab(dd[j], al[kq], bhf[j][kq]);
                }
            #pragma unroll
            for (int j = 0; j < 2; j++) {
                int c = 16 * wid + 8 * j + 2 * (lane & 3);
                #pragma unroll
                for (int h = 0; h < 2; h++) {
                    int gr = mt * 16 + (lane >> 2) + 8 * h;
                    if (gr < m) {
                        int rw = lrow[gr];
                        acc[rw * 72 + c]     += dd[j][2 * h];
                        acc[rw * 72 + c + 1] += dd[j][2 * h + 1];
                    }
                }
            }
        }
    }
    __syncthreads();
    // BN2 + SiLU -> split bf16 A3 tile (into gather region)
    const float* sc2 = (const float*)(sm + O_SC2);
    const float* tb2 = (const float*)(sm + O_TB2);
    #pragma unroll
    for (int i = 0; i < 32; i++) {
        int idx = t + 128 * i, r = idx >> 5, p = idx & 31;
        float x0 = acc[r * 72 + 2 * p] * sc2[2 * p] + tb2[2 * p];
        float x1 = acc[r * 72 + 2 * p + 1] * sc2[2 * p + 1] + tb2[2 * p + 1];
        x0 = silu(x0); x1 = silu(x1);
        __nv_bfloat16 h0 = __float2bfloat16(x0), h1 = __float2bfloat16(x1);
        *(unsigned*)(sm + O_GHI + r * 144 + p * 4) = pack2(h0, h1);
        *(unsigned*)(sm + O_GLO + r * 144 + p * 4) =
            pack2(__float2bfloat16(x0 - __bfloat162float(h0)),
                  __float2bfloat16(x1 - __bfloat162float(h1)));
    }
    __syncthreads();
    {   // W3 image copy into (dead) ACC region (4352 u32 — FIX: was 17 iters)
        const unsigned* sh = (const unsigned*)gW3hi;
        const unsigned* sl = (const unsigned*)gW3lo;
        unsigned* dh = (unsigned*)(sm + O_W3HI);
        unsigned* dl = (unsigned*)(sm + O_W3LO);
        #pragma unroll
        for (int i = 0; i < 34; i++) { dh[t + 128 * i] = sh[t + 128 * i]; dl[t + 128 * i] = sl[t + 128 * i]; }
    }
    __syncthreads();
    // cv3: warp = 32 rows x all 128 cols (per-n8 streaming epilogue)
    const float* sc3 = (const float*)(sm + O_SC3);
    const float* tb3 = (const float*)(sm + O_TB3);
    unsigned ah[2][4][4], al[2][4][4];
    #pragma unroll
    for (int mt = 0; mt < 2; mt++)
        #pragma unroll
        for (int kq = 0; kq < 4; kq++) {
            uint32_t a = sb + O_GHI + (wid * 32 + mt * 16 + arow) * 144 + kq * 32 + acol;
            ldmA(ah[mt][kq], a);
            ldmA(al[mt][kq], a + (O_GLO - O_GHI));
        }
    #pragma unroll
    for (int half = 0; half < 2; half++)
        #pragma unroll
        for (int n8 = 0; n8 < 8; n8++) {
            unsigned b_h[4][2], b_l[4][2];
            #pragma unroll
            for (int kq = 0; kq < 4; kq++) {
                uint32_t a = sb + O_W3HI + (kq * 16 + brow) * 272 + half * 128 + n8 * 16;
                ldmB(b_h[kq], a);
                ldmB(b_l[kq], a + (O_W3LO - O_W3HI));
            }
            float dd[2][4] = {};
            #pragma unroll
            for (int mt = 0; mt < 2; mt++)
                #pragma unroll
                for (int kq = 0; kq < 4; kq++) {
                    mmab(dd[mt], ah[mt][kq], b_h[kq]);
                    mmab(dd[mt], ah[mt][kq], b_l[kq]);
                    mmab(dd[mt], al[mt][kq], b_h[kq]);
                }
            int c = 64 * half + 8 * n8 + 2 * (lane & 3);
            float s0 = sc3[c], s1 = sc3[c + 1], t0 = tb3[c], t1 = tb3[c + 1];
            #pragma unroll
            for (int mt = 0; mt < 2; mt++)
                #pragma unroll
                for (int h = 0; h < 2; h++) {
                    int site = base + wid * 32 + mt * 16 + (lane >> 2) + 8 * h;
                    if (site < NS) {
                        float2 f = *(const float2*)(feat + (size_t)site * 128 + c);
                        float o0 = silu(dd[mt][2 * h] * s0 + t0 + f.x);
                        float o1 = silu(dd[mt][2 * h + 1] * s1 + t1 + f.y);
                        *(float2*)(out + (size_t)site * 128 + c) = make_float2(o0, o1);
                    }
                }
        }
}

// ============================================================================
extern "C" void kernel_launch(void* const* d_in, const int* in_sizes, int n_in,
                              void* d_out, int out_size) {
    const float* feat = (const float*)d_in[0];
    const int*   nbr  = (const int*)d_in[1];
    const float* W1 = (const float*)d_in[2];
    const float* W2 = (const float*)d_in[3];
    const float* W3 = (const float*)d_in[4];
    const float* g1 = (const float*)d_in[5];
    const float* b1 = (const float*)d_in[6];
    const float* m1 = (const float*)d_in[7];
    const float* v1 = (const float*)d_in[8];
    const float* g2 = (const float*)d_in[9];
    const float* b2 = (const float*)d_in[10];
    const float* m2 = (const float*)d_in[11];
    const float* v2 = (const float*)d_in[12];
    const float* g3 = (const float*)d_in[13];
    const float* b3 = (const float*)d_in[14];
    const float* m3 = (const float*)d_in[15];
    const float* v3 = (const float*)d_in[16];
    float* out = (float*)d_out;

    cudaFuncSetAttribute(k1, cudaFuncAttributeMaxDynamicSharedMemorySize, SM1);
    cudaFuncSetAttribute(k2, cudaFuncAttributeMaxDynamicSharedMemorySize, SM2);

    int grid = (NS + 127) / 128;   // 3907
    k0<<<232, 256>>>(W1, W2, W3);
    k1<<<grid, 128, SM1>>>(feat, g1, b1, m1, v1);
    k2<<<grid, 128, SM2>>>(feat, nbr, g2, b2, m2, v2, g3, b3, m3, v3, out);
}

// round 7
// speedup vs baseline: 1.5108x; 1.3468x over previous
#include <cuda_runtime.h>
#include <cuda_bf16.h>
#include <cstdint>

#define NS 500000
#define EPS 1e-5f

// split-bf16 hidden activations: 2 channels packed per u32, 32 u32 per site
__device__ __align__(16) unsigned g_hhi[NS * 32];
__device__ __align__(16) unsigned g_hlo[NS * 32];
// padded ldmatrix-ready weight images: [K][N+pad] u16, built by k0
__device__ __align__(16) unsigned short gW1hi[128 * 72], gW1lo[128 * 72];
__device__ __align__(16) unsigned short gW2hi[9 * 64 * 72], gW2lo[9 * 64 * 72];
__device__ __align__(16) unsigned short gW3hi[64 * 136], gW3lo[64 * 136];

__device__ __forceinline__ uint32_t s2u(const void* p) {
    uint32_t a;
    asm("{ .reg .u64 t; cvta.to.shared.u64 t, %1; cvt.u32.u64 %0, t; }" : "=r"(a) : "l"(p));
    return a;
}
__device__ __forceinline__ float silu(float x) { return x / (1.0f + __expf(-x)); }
__device__ __forceinline__ unsigned pack2(__nv_bfloat16 a, __nv_bfloat16 b) {
    return (unsigned)__bfloat16_as_ushort(a) | ((unsigned)__bfloat16_as_ushort(b) << 16);
}
__device__ __forceinline__ void ldmA(unsigned r[4], uint32_t a) {
    asm volatile("ldmatrix.sync.aligned.m8n8.x4.shared.b16 {%0,%1,%2,%3}, [%4];"
                 : "=r"(r[0]), "=r"(r[1]), "=r"(r[2]), "=r"(r[3]) : "r"(a));
}
__device__ __forceinline__ void ldmB(unsigned r[2], uint32_t a) {
    asm volatile("ldmatrix.sync.aligned.m8n8.x2.trans.shared.b16 {%0,%1}, [%2];"
                 : "=r"(r[0]), "=r"(r[1]) : "r"(a));
}
__device__ __forceinline__ void mmab(float d[4], const unsigned a[4], const unsigned b[2]) {
    asm volatile(
        "mma.sync.aligned.m16n8k16.row.col.f32.bf16.bf16.f32 "
        "{%0,%1,%2,%3},{%4,%5,%6,%7},{%8,%9},{%0,%1,%2,%3};"
        : "+f"(d[0]), "+f"(d[1]), "+f"(d[2]), "+f"(d[3])
        : "r"(a[0]), "r"(a[1]), "r"(a[2]), "r"(a[3]), "r"(b[0]), "r"(b[1]));
}

// ============================================================================
// k0: transpose + hi/lo-split + pad weights into ldmatrix B images [K][N+pad]
// ============================================================================
__global__ void k0(const float* __restrict__ W1, const float* __restrict__ W2,
                   const float* __restrict__ W3) {
    int i = blockIdx.x * 256 + threadIdx.x;
    float x;
    unsigned short *dh, *dl;
    int idx;
    if (i < 9216) {                       // W1: [128k][64n] -> [128][72]
        int k = i / 72, n = i % 72;
        x = (n < 64) ? W1[k * 64 + n] : 0.f;
        idx = i; dh = gW1hi; dl = gW1lo;
    } else if (i < 50688) {               // W2[kk]: [64k][64n] -> [9][64][72]
        int j = i - 9216;
        int kk = j / 4608, r = j % 4608, ki = r / 72, n = r % 72;
        x = (n < 64) ? W2[kk * 4096 + ki * 64 + n] : 0.f;
        idx = j; dh = gW2hi; dl = gW2lo;
    } else if (i < 59392) {               // W3: [64k][128n] -> [64][136]
        int j = i - 50688;
        int ki = j / 136, n = j % 136;
        x = (n < 128) ? W3[ki * 128 + n] : 0.f;
        idx = j; dh = gW3hi; dl = gW3lo;
    } else return;
    __nv_bfloat16 h = __float2bfloat16(x);
    dh[idx] = __bfloat16_as_ushort(h);
    dl[idx] = __bfloat16_as_ushort(__float2bfloat16(x - __bfloat162float(h)));
}

// ============================================================================
// k1: h = silu(bn1(feat @ W1))  [128 rows/block, 256 thr, warp = 16 rows]
// ============================================================================
#define O_B1HI 0
#define O_B1LO 18432
#define O_A1HI 36864
#define O_A1LO 47104
#define O_P1SC 57344
#define O_P1TB 57600
#define SM1    57856

__global__ __launch_bounds__(256) void k1(
    const float* __restrict__ feat,
    const float* __restrict__ g1, const float* __restrict__ b1,
    const float* __restrict__ m1, const float* __restrict__ v1)
{
    extern __shared__ char sm[];
    uint32_t sb = s2u(sm);
    int t = threadIdx.x, wid = t >> 5, lane = t & 31;
    int base = blockIdx.x * 128;

    {   // W1 images: 4608 u32 each
        const unsigned* sh = (const unsigned*)gW1hi;
        const unsigned* sl = (const unsigned*)gW1lo;
        unsigned* dh = (unsigned*)(sm + O_B1HI);
        unsigned* dl = (unsigned*)(sm + O_B1LO);
        #pragma unroll
        for (int i = 0; i < 18; i++) { dh[t + 256 * i] = sh[t + 256 * i]; dl[t + 256 * i] = sl[t + 256 * i]; }
    }
    if (t < 64) {
        float s = g1[t] * rsqrtf(v1[t] + EPS);
        ((float*)(sm + O_P1SC))[t] = s;
        ((float*)(sm + O_P1TB))[t] = b1[t] - m1[t] * s;
    }

    float d[8][4] = {};
    int arow = ((lane >> 3) & 1) * 8 + (lane & 7);
    int acol = (lane >> 4) * 16;
    int brow = arow;

    for (int kc = 0; kc < 4; kc++) {
        __syncthreads();
        // stage A chunk (K=32) split bf16, row stride 80B
        #pragma unroll
        for (int i = 0; i < 8; i++) {
            int idx = t + 256 * i, r = idx >> 4, p = idx & 15;
            int site = base + r;
            float2 f = (site < NS) ? ((const float2*)feat)[(size_t)site * 64 + kc * 16 + p]
                                   : make_float2(0.f, 0.f);
            __nv_bfloat16 h0 = __float2bfloat16(f.x), h1 = __float2bfloat16(f.y);
            *(unsigned*)(sm + O_A1HI + r * 80 + p * 4) = pack2(h0, h1);
            *(unsigned*)(sm + O_A1LO + r * 80 + p * 4) =
                pack2(__float2bfloat16(f.x - __bfloat162float(h0)),
                      __float2bfloat16(f.y - __bfloat162float(h1)));
        }
        __syncthreads();
        unsigned ah[2][4], al[2][4];
        #pragma unroll
        for (int kq = 0; kq < 2; kq++) {
            uint32_t a = sb + O_A1HI + (wid * 16 + arow) * 80 + kq * 32 + acol;
            ldmA(ah[kq], a);
            ldmA(al[kq], a + (O_A1LO - O_A1HI));
        }
        #pragma unroll
        for (int n8 = 0; n8 < 8; n8++) {
            unsigned bh[2][2], bl[2][2];
            #pragma unroll
            for (int kq = 0; kq < 2; kq++) {
                uint32_t a = sb + O_B1HI + (kc * 32 + kq * 16 + brow) * 144 + n8 * 16;
                ldmB(bh[kq], a);
                ldmB(bl[kq], a + (O_B1LO - O_B1HI));
            }
            #pragma unroll
            for (int kq = 0; kq < 2; kq++) {
                mmab(d[n8], ah[kq], bh[kq]);
                mmab(d[n8], ah[kq], bl[kq]);
                mmab(d[n8], al[kq], bh[kq]);
            }
        }
    }
    // BN1 + SiLU + split, direct global store
    const float* sc = (const float*)(sm + O_P1SC);
    const float* tb = (const float*)(sm + O_P1TB);
    #pragma unroll
    for (int n8 = 0; n8 < 8; n8++) {
        int c = 8 * n8 + 2 * (lane & 3);
        float s0 = sc[c], s1 = sc[c + 1], t0 = tb[c], t1 = tb[c + 1];
        #pragma unroll
        for (int h = 0; h < 2; h++) {
            int site = base + wid * 16 + (lane >> 2) + 8 * h;
            if (site < NS) {
                float o0 = silu(d[n8][2 * h] * s0 + t0);
                float o1 = silu(d[n8][2 * h + 1] * s1 + t1);
                __nv_bfloat16 x0 = __float2bfloat16(o0), x1 = __float2bfloat16(o1);
                g_hhi[(size_t)site * 32 + (c >> 1)] = pack2(x0, x1);
                g_hlo[(size_t)site * 32 + (c >> 1)] =
                    pack2(__float2bfloat16(o0 - __bfloat162float(x0)),
                          __float2bfloat16(o1 - __bfloat162float(x1)));
            }
        }
    }
}

// ============================================================================
// k2: cv2 (compacted rulebook conv, smem f32 scatter-accum) + BN2/SiLU +
//     cv3 (+BN3+residual+SiLU).  256 threads, 8 warps.
// ============================================================================
#define O_ACC  0          // f32 [128][72]
#define O_GHI  36864      // u16 [128][72] gather / A3 tile
#define O_GLO  55296
#define O_WHI  73728      // u16 [64][72]  W2[k]
#define O_WLO  82944
#define O_LROW 92160
#define O_LGAT 92672
#define O_CNT  93184
#define O_SC2  93200
#define O_TB2  93456
#define O_SC3  93712
#define O_TB3  94224
#define SM2    94736
#define O_W3HI 0          // reuse ACC region: u16 [64][136]
#define O_W3LO 17408

__global__ __launch_bounds__(256) void k2(
    const float* __restrict__ feat, const int* __restrict__ nbr,
    const float* __restrict__ g2, const float* __restrict__ b2,
    const float* __restrict__ m2, const float* __restrict__ v2,
    const float* __restrict__ g3, const float* __restrict__ b3,
    const float* __restrict__ m3, const float* __restrict__ v3,
    float* __restrict__ out)
{
    extern __shared__ char sm[];
    uint32_t sb = s2u(sm);
    int t = threadIdx.x, wid = t >> 5, lane = t & 31;
    int base = blockIdx.x * 128;
    int* lrow = (int*)(sm + O_LROW);
    int* lgat = (int*)(sm + O_LGAT);
    int* cnt = (int*)(sm + O_CNT);
    float* acc = (float*)(sm + O_ACC);

    if (t < 64) {
        float s = g2[t] * rsqrtf(v2[t] + EPS);
        ((float*)(sm + O_SC2))[t] = s;
        ((float*)(sm + O_TB2))[t] = b2[t] - m2[t] * s;
    }
    if (t < 128) {
        float s = g3[t] * rsqrtf(v3[t] + EPS);
        ((float*)(sm + O_SC3))[t] = s;
        ((float*)(sm + O_TB3))[t] = b3[t] - m3[t] * s;
    }
    for (int i = 0; i < 36; i++) acc[t + 256 * i] = 0.f;
    if (t == 0) *cnt = 0;

    int arow = ((lane >> 3) & 1) * 8 + (lane & 7);
    int acol = (lane >> 4) * 16;
    int brow = arow;

    for (int k = 0; k < 9; k++) {
        __syncthreads();
        {   // W2[k] image copy (2304 u32 per array)
            const unsigned* sh = (const unsigned*)(gW2hi + k * 4608);
            const unsigned* sl = (const unsigned*)(gW2lo + k * 4608);
            unsigned* dh = (unsigned*)(sm + O_WHI);
            unsigned* dl = (unsigned*)(sm + O_WLO);
            #pragma unroll
            for (int i = 0; i < 9; i++) { dh[t + 256 * i] = sh[t + 256 * i]; dl[t + 256 * i] = sl[t + 256 * i]; }
        }
        if (t < 128) {   // compact valid neighbors (4 warps)
            int site = base + t;
            int id = (site < NS) ? __ldg(&nbr[(size_t)k * NS + site]) : NS;
            bool val = id < NS;
            unsigned msk = __ballot_sync(0xffffffffu, val);
            int wb = 0;
            if (lane == 0 && msk) wb = atomicAdd(cnt, __popc(msk));
            wb = __shfl_sync(0xffffffffu, wb, 0);
            if (val) {
                int p = wb + __popc(msk & ((1u << lane) - 1u));
                lrow[p] = t; lgat[p] = id;
            }
        }
        __syncthreads();
        int m = *cnt;
        for (int q = t; q < m * 32; q += 256) {   // gather split-bf16 rows
            int r = q >> 5, w = q & 31;
            int id = lgat[r];
            *(unsigned*)(sm + O_GHI + r * 144 + w * 4) = g_hhi[(size_t)id * 32 + w];
            *(unsigned*)(sm + O_GLO + r * 144 + w * 4) = g_hlo[(size_t)id * 32 + w];
        }
        if (t == 0) *cnt = 0;
        __syncthreads();
        int mtiles = (m + 15) >> 4;
        // warp wid owns output cols [8*wid, 8*wid+8)
        unsigned bhf[4][2], blf[4][2];
        #pragma unroll
        for (int kq = 0; kq < 4; kq++) {
            uint32_t a = sb + O_WHI + (kq * 16 + brow) * 144 + wid * 16;
            ldmB(bhf[kq], a);
            ldmB(blf[kq], a + (O_WLO - O_WHI));
        }
        for (int mt = 0; mt < mtiles; mt++) {
            unsigned ah[4][4], al[4][4];
            #pragma unroll
            for (int kq = 0; kq < 4; kq++) {
                uint32_t a = sb + O_GHI + (mt * 16 + arow) * 144 + kq * 32 + acol;
                ldmA(ah[kq], a);
                ldmA(al[kq], a + (O_GLO - O_GHI));
            }
            float dd[4] = {};
            #pragma unroll
            for (int kq = 0; kq < 4; kq++) {
                mmab(dd, ah[kq], bhf[kq]);
                mmab(dd, ah[kq], blf[kq]);
                mmab(dd, al[kq], bhf[kq]);
            }
            int c = 8 * wid + 2 * (lane & 3);
            #pragma unroll
            for (int h = 0; h < 2; h++) {
                int gr = mt * 16 + (lane >> 2) + 8 * h;
                if (gr < m) {
                    int rw = lrow[gr];
                    acc[rw * 72 + c]     += dd[2 * h];
                    acc[rw * 72 + c + 1] += dd[2 * h + 1];
                }
            }
        }
    }
    __syncthreads();
    // BN2 + SiLU -> split bf16 A3 tile (into gather region)
    const float* sc2 = (const float*)(sm + O_SC2);
    const float* tb2 = (const float*)(sm + O_TB2);
    #pragma unroll
    for (int i = 0; i < 16; i++) {
        int idx = t + 256 * i, r = idx >> 5, p = idx & 31;
        float x0 = acc[r * 72 + 2 * p] * sc2[2 * p] + tb2[2 * p];
        float x1 = acc[r * 72 + 2 * p + 1] * sc2[2 * p + 1] + tb2[2 * p + 1];
        x0 = silu(x0); x1 = silu(x1);
        __nv_bfloat16 h0 = __float2bfloat16(x0), h1 = __float2bfloat16(x1);
        *(unsigned*)(sm + O_GHI + r * 144 + p * 4) = pack2(h0, h1);
        *(unsigned*)(sm + O_GLO + r * 144 + p * 4) =
            pack2(__float2bfloat16(x0 - __bfloat162float(h0)),
                  __float2bfloat16(x1 - __bfloat162float(h1)));
    }
    __syncthreads();
    {   // W3 image copy into (dead) ACC region (4352 u32 = 17*256)
        const unsigned* sh = (const unsigned*)gW3hi;
        const unsigned* sl = (const unsigned*)gW3lo;
        unsigned* dh = (unsigned*)(sm + O_W3HI);
        unsigned* dl = (unsigned*)(sm + O_W3LO);
        #pragma unroll
        for (int i = 0; i < 17; i++) { dh[t + 256 * i] = sh[t + 256 * i]; dl[t + 256 * i] = sl[t + 256 * i]; }
    }
    __syncthreads();
    // cv3: warp = 16 rows x all 128 cols (per-n8 streaming epilogue)
    const float* sc3 = (const float*)(sm + O_SC3);
    const float* tb3 = (const float*)(sm + O_TB3);
    unsigned ah[4][4], al[4][4];
    #pragma unroll
    for (int kq = 0; kq < 4; kq++) {
        uint32_t a = sb + O_GHI + (wid * 16 + arow) * 144 + kq * 32 + acol;
        ldmA(ah[kq], a);
        ldmA(al[kq], a + (O_GLO - O_GHI));
    }
    #pragma unroll
    for (int half = 0; half < 2; half++)
        #pragma unroll
        for (int n8 = 0; n8 < 8; n8++) {
            unsigned b_h[4][2], b_l[4][2];
            #pragma unroll
            for (int kq = 0; kq < 4; kq++) {
                uint32_t a = sb + O_W3HI + (kq * 16 + brow) * 272 + half * 128 + n8 * 16;
                ldmB(b_h[kq], a);
                ldmB(b_l[kq], a + (O_W3LO - O_W3HI));
            }
            float dd[4] = {};
            #pragma unroll
            for (int kq = 0; kq < 4; kq++) {
                mmab(dd, ah[kq], b_h[kq]);
                mmab(dd, ah[kq], b_l[kq]);
                mmab(dd, al[kq], b_h[kq]);
            }
            int c = 64 * half + 8 * n8 + 2 * (lane & 3);
            float s0 = sc3[c], s1 = sc3[c + 1], t0 = tb3[c], t1 = tb3[c + 1];
            #pragma unroll
            for (int h = 0; h < 2; h++) {
                int site = base + wid * 16 + (lane >> 2) + 8 * h;
                if (site < NS) {
                    float2 f = *(const float2*)(feat + (size_t)site * 128 + c);
                    float o0 = silu(dd[2 * h] * s0 + t0 + f.x);
                    float o1 = silu(dd[2 * h + 1] * s1 + t1 + f.y);
                    *(float2*)(out + (size_t)site * 128 + c) = make_float2(o0, o1);
                }
            }
        }
}

// ============================================================================
extern "C" void kernel_launch(void* const* d_in, const int* in_sizes, int n_in,
                              void* d_out, int out_size) {
    const float* feat = (const float*)d_in[0];
    const int*   nbr  = (const int*)d_in[1];
    const float* W1 = (const float*)d_in[2];
    const float* W2 = (const float*)d_in[3];
    const float* W3 = (const float*)d_in[4];
    const float* g1 = (const float*)d_in[5];
    const float* b1 = (const float*)d_in[6];
    const float* m1 = (const float*)d_in[7];
    const float* v1 = (const float*)d_in[8];
    const float* g2 = (const float*)d_in[9];
    const float* b2 = (const float*)d_in[10];
    const float* m2 = (const float*)d_in[11];
    const float* v2 = (const float*)d_in[12];
    const float* g3 = (const float*)d_in[13];
    const float* b3 = (const float*)d_in[14];
    const float* m3 = (const float*)d_in[15];
    const float* v3 = (const float*)d_in[16];
    float* out = (float*)d_out;

    cudaFuncSetAttribute(k1, cudaFuncAttributeMaxDynamicSharedMemorySize, SM1);
    cudaFuncSetAttribute(k2, cudaFuncAttributeMaxDynamicSharedMemorySize, SM2);

    int grid = (NS + 127) / 128;   // 3907
    k0<<<232, 256>>>(W1, W2, W3);
    k1<<<grid, 256, SM1>>>(feat, g1, b1, m1, v1);
    k2<<<grid, 256, SM2>>>(feat, nbr, g2, b2, m2, v2, g3, b3, m3, v3, out);
}

// round 8
// speedup vs baseline: 2.0529x; 1.3588x over previous
#include <cuda_runtime.h>
#include <cuda_bf16.h>
#include <cstdint>

#define NS 500000
#define EPS 1e-5f

// split-bf16 hidden activations: 2 channels packed per u32, 32 u32 per site
__device__ __align__(16) unsigned g_hhi[NS * 32];
__device__ __align__(16) unsigned g_hlo[NS * 32];
// padded ldmatrix-ready weight images: [K][N+pad] u16, built by k0
__device__ __align__(16) unsigned short gW1hi[128 * 72], gW1lo[128 * 72];
__device__ __align__(16) unsigned short gW2hi[9 * 64 * 72], gW2lo[9 * 64 * 72];
__device__ __align__(16) unsigned short gW3hi[64 * 136], gW3lo[64 * 136];

__device__ __forceinline__ uint32_t s2u(const void* p) {
    uint32_t a;
    asm("{ .reg .u64 t; cvta.to.shared.u64 t, %1; cvt.u32.u64 %0, t; }" : "=r"(a) : "l"(p));
    return a;
}
__device__ __forceinline__ float silu(float x) { return x / (1.0f + __expf(-x)); }
// truncation split: hi = top 16 bits (exact), lo = rn(x - hi). 2 elements at once.
__device__ __forceinline__ void split2(float x0, float x1, unsigned& hi, unsigned& lo) {
    unsigned u0 = __float_as_uint(x0), u1 = __float_as_uint(x1);
    asm("prmt.b32 %0, %1, %2, 0x7632;" : "=r"(hi) : "r"(u0), "r"(u1));
    float l0 = x0 - __uint_as_float(u0 & 0xffff0000u);
    float l1 = x1 - __uint_as_float(u1 & 0xffff0000u);
    asm("cvt.rn.bf16x2.f32 %0, %1, %2;" : "=r"(lo) : "f"(l1), "f"(l0));
}
__device__ __forceinline__ void cpa16(uint32_t dst, const void* src) {
    asm volatile("cp.async.ca.shared.global [%0], [%1], 16;" :: "r"(dst), "l"(src));
}
#define CP_COMMIT() asm volatile("cp.async.commit_group;" ::: "memory")
#define CP_WAIT0()  asm volatile("cp.async.wait_group 0;" ::: "memory")
__device__ __forceinline__ void ldmA(unsigned r[4], uint32_t a) {
    asm volatile("ldmatrix.sync.aligned.m8n8.x4.shared.b16 {%0,%1,%2,%3}, [%4];"
                 : "=r"(r[0]), "=r"(r[1]), "=r"(r[2]), "=r"(r[3]) : "r"(a));
}
__device__ __forceinline__ void ldmB(unsigned r[2], uint32_t a) {
    asm volatile("ldmatrix.sync.aligned.m8n8.x2.trans.shared.b16 {%0,%1}, [%2];"
                 : "=r"(r[0]), "=r"(r[1]) : "r"(a));
}
__device__ __forceinline__ void mmab(float d[4], const unsigned a[4], const unsigned b[2]) {
    asm volatile(
        "mma.sync.aligned.m16n8k16.row.col.f32.bf16.bf16.f32 "
        "{%0,%1,%2,%3},{%4,%5,%6,%7},{%8,%9},{%0,%1,%2,%3};"
        : "+f"(d[0]), "+f"(d[1]), "+f"(d[2]), "+f"(d[3])
        : "r"(a[0]), "r"(a[1]), "r"(a[2]), "r"(a[3]), "r"(b[0]), "r"(b[1]));
}

// ============================================================================
// k0: transpose + hi/lo-split + pad weights into ldmatrix B images [K][N+pad]
// ============================================================================
__global__ void k0(const float* __restrict__ W1, const float* __restrict__ W2,
                   const float* __restrict__ W3) {
    int i = blockIdx.x * 256 + threadIdx.x;
    float x;
    unsigned short *dh, *dl;
    int idx;
    if (i < 9216) {                       // W1: [128k][64n] -> [128][72]
        int k = i / 72, n = i % 72;
        x = (n < 64) ? W1[k * 64 + n] : 0.f;
        idx = i; dh = gW1hi; dl = gW1lo;
    } else if (i < 50688) {               // W2[kk]: [64k][64n] -> [9][64][72]
        int j = i - 9216;
        int kk = j / 4608, r = j % 4608, ki = r / 72, n = r % 72;
        x = (n < 64) ? W2[kk * 4096 + ki * 64 + n] : 0.f;
        idx = j; dh = gW2hi; dl = gW2lo;
    } else if (i < 59392) {               // W3: [64k][128n] -> [64][136]
        int j = i - 50688;
        int ki = j / 136, n = j % 136;
        x = (n < 128) ? W3[ki * 128 + n] : 0.f;
        idx = j; dh = gW3hi; dl = gW3lo;
    } else return;
    __nv_bfloat16 h = __float2bfloat16(x);
    dh[idx] = __bfloat16_as_ushort(h);
    dl[idx] = __bfloat16_as_ushort(__float2bfloat16(x - __bfloat162float(h)));
}

// ============================================================================
// k1: h = silu(bn1(feat @ W1))  [128 rows/block, 256 thr, warp = 16 rows]
// ============================================================================
#define O_B1HI 0
#define O_B1LO 18432
#define O_A1HI 36864
#define O_A1LO 47104
#define O_P1SC 57344
#define O_P1TB 57600
#define SM1    57856

__global__ __launch_bounds__(256, 3) void k1(
    const float* __restrict__ feat,
    const float* __restrict__ g1, const float* __restrict__ b1,
    const float* __restrict__ m1, const float* __restrict__ v1)
{
    extern __shared__ char sm[];
    uint32_t sb = s2u(sm);
    int t = threadIdx.x, wid = t >> 5, lane = t & 31;
    int base = blockIdx.x * 128;

    // W1 images via cp.async: 1152 16B-ops per array
    for (int q = t; q < 2304; q += 256) {
        if (q < 1152) cpa16(sb + O_B1HI + q * 16, gW1hi + q * 8);
        else          cpa16(sb + O_B1LO + (q - 1152) * 16, gW1lo + (q - 1152) * 8);
    }
    CP_COMMIT();
    if (t < 64) {
        float s = g1[t] * rsqrtf(v1[t] + EPS);
        ((float*)(sm + O_P1SC))[t] = s;
        ((float*)(sm + O_P1TB))[t] = b1[t] - m1[t] * s;
    }

    float d[8][4] = {};
    int arow = ((lane >> 3) & 1) * 8 + (lane & 7);
    int acol = (lane >> 4) * 16;
    int brow = arow;

    for (int kc = 0; kc < 4; kc++) {
        __syncthreads();
        // stage A chunk (K=32) split bf16, row stride 80B, float4 loads
        #pragma unroll
        for (int i = 0; i < 4; i++) {
            int idx = t + 256 * i, r = idx >> 3, p = idx & 7;
            int site = base + r;
            float4 f = (site < NS) ? ((const float4*)feat)[(size_t)site * 32 + kc * 8 + p]
                                   : make_float4(0.f, 0.f, 0.f, 0.f);
            unsigned h0, l0, h1, l1;
            split2(f.x, f.y, h0, l0);
            split2(f.z, f.w, h1, l1);
            *(uint2*)(sm + O_A1HI + r * 80 + p * 8) = make_uint2(h0, h1);
            *(uint2*)(sm + O_A1LO + r * 80 + p * 8) = make_uint2(l0, l1);
        }
        CP_WAIT0();
        __syncthreads();
        unsigned ah[2][4], al[2][4];
        #pragma unroll
        for (int kq = 0; kq < 2; kq++) {
            uint32_t a = sb + O_A1HI + (wid * 16 + arow) * 80 + kq * 32 + acol;
            ldmA(ah[kq], a);
            ldmA(al[kq], a + (O_A1LO - O_A1HI));
        }
        #pragma unroll
        for (int n8 = 0; n8 < 8; n8++) {
            unsigned bh[2][2], bl[2][2];
            #pragma unroll
            for (int kq = 0; kq < 2; kq++) {
                uint32_t a = sb + O_B1HI + (kc * 32 + kq * 16 + brow) * 144 + n8 * 16;
                ldmB(bh[kq], a);
                ldmB(bl[kq], a + (O_B1LO - O_B1HI));
            }
            #pragma unroll
            for (int kq = 0; kq < 2; kq++) {
                mmab(d[n8], ah[kq], bh[kq]);
                mmab(d[n8], ah[kq], bl[kq]);
                mmab(d[n8], al[kq], bh[kq]);
            }
        }
    }
    // BN1 + SiLU + split, direct global store
    const float* sc = (const float*)(sm + O_P1SC);
    const float* tb = (const float*)(sm + O_P1TB);
    #pragma unroll
    for (int n8 = 0; n8 < 8; n8++) {
        int c = 8 * n8 + 2 * (lane & 3);
        float s0 = sc[c], s1 = sc[c + 1], t0 = tb[c], t1 = tb[c + 1];
        #pragma unroll
        for (int h = 0; h < 2; h++) {
            int site = base + wid * 16 + (lane >> 2) + 8 * h;
            if (site < NS) {
                float o0 = silu(d[n8][2 * h] * s0 + t0);
                float o1 = silu(d[n8][2 * h + 1] * s1 + t1);
                unsigned hw, lw;
                split2(o0, o1, hw, lw);
                g_hhi[(size_t)site * 32 + (c >> 1)] = hw;
                g_hlo[(size_t)site * 32 + (c >> 1)] = lw;
            }
        }
    }
}

// ============================================================================
// k2: cv2 (compacted rulebook conv, smem f32 scatter-accum) + BN2/SiLU +
//     cv3 (+BN3+residual+SiLU).  256 threads; lists precomputed; cp.async.
// ============================================================================
#define O_ACC  0          // f32 [128][72]
#define O_GHI  36864      // u16 [128][72] gather / A3 tile
#define O_GLO  55296
#define O_WHI  73728      // u16 [64][72]  W2[k]
#define O_WLO  82944
#define O_LR   92160      // int [9][128] compacted block-row
#define O_LG   96768      // int [9][128] compacted gather id
#define O_CN   101376     // int [9] counts (+pad)
#define O_SC2  101440
#define O_TB2  101696
#define O_SC3  101952
#define O_TB3  102464
#define SM2    102976
#define O_W3HI 0          // reuse ACC region: u16 [64][136]
#define O_W3LO 17408

__global__ __launch_bounds__(256) void k2(
    const float* __restrict__ feat, const int* __restrict__ nbr,
    const float* __restrict__ g2, const float* __restrict__ b2,
    const float* __restrict__ m2, const float* __restrict__ v2,
    const float* __restrict__ g3, const float* __restrict__ b3,
    const float* __restrict__ m3, const float* __restrict__ v3,
    float* __restrict__ out)
{
    extern __shared__ char sm[];
    uint32_t sb = s2u(sm);
    int t = threadIdx.x, wid = t >> 5, lane = t & 31;
    int base = blockIdx.x * 128;
    int* lrow = (int*)(sm + O_LR);
    int* lgat = (int*)(sm + O_LG);
    int* cnt9 = (int*)(sm + O_CN);
    float* acc = (float*)(sm + O_ACC);

    if (t < 64) {
        float s = g2[t] * rsqrtf(v2[t] + EPS);
        ((float*)(sm + O_SC2))[t] = s;
        ((float*)(sm + O_TB2))[t] = b2[t] - m2[t] * s;
    }
    if (t < 128) {
        float s = g3[t] * rsqrtf(v3[t] + EPS);
        ((float*)(sm + O_SC3))[t] = s;
        ((float*)(sm + O_TB3))[t] = b3[t] - m3[t] * s;
    }
    #pragma unroll
    for (int i = 0; i < 36; i++) acc[t + 256 * i] = 0.f;

    // precompute all 9 compaction lists: warp w handles offsets w, w+8
    for (int k = wid; k < 9; k += 8) {
        int cbase = 0;
        #pragma unroll
        for (int g = 0; g < 4; g++) {
            int site = base + g * 32 + lane;
            int id = (site < NS) ? __ldg(&nbr[(size_t)k * NS + site]) : NS;
            bool val = id < NS;
            unsigned msk = __ballot_sync(0xffffffffu, val);
            if (val) {
                int p = cbase + __popc(msk & ((1u << lane) - 1u));
                lrow[k * 128 + p] = g * 32 + lane;
                lgat[k * 128 + p] = id;
            }
            cbase += __popc(msk);
        }
        if (lane == 0) cnt9[k] = cbase;
    }
    __syncthreads();

    int arow = ((lane >> 3) & 1) * 8 + (lane & 7);
    int acol = (lane >> 4) * 16;
    int brow = arow;

    for (int k = 0; k < 9; k++) {
        int m = cnt9[k];
        // async gather of valid h rows (hi: segs 0-7, lo: segs 8-15)
        for (int q = t; q < m * 16; q += 256) {
            int r = q >> 4, s = q & 15;
            int id = lgat[k * 128 + r];
            if (s < 8) cpa16(sb + O_GHI + r * 144 + s * 16, g_hhi + (size_t)id * 32 + s * 4);
            else       cpa16(sb + O_GLO + r * 144 + (s - 8) * 16, g_hlo + (size_t)id * 32 + (s - 8) * 4);
        }
        // async W2[k] image copy (576 16B-ops per array)
        for (int q = t; q < 1152; q += 256) {
            if (q < 576) cpa16(sb + O_WHI + q * 16, gW2hi + k * 4608 + q * 8);
            else         cpa16(sb + O_WLO + (q - 576) * 16, gW2lo + k * 4608 + (q - 576) * 8);
        }
        CP_COMMIT();
        CP_WAIT0();
        __syncthreads();

        int mtiles = (m + 15) >> 4;
        // warp wid owns output cols [8*wid, 8*wid+8)
        unsigned bhf[4][2], blf[4][2];
        #pragma unroll
        for (int kq = 0; kq < 4; kq++) {
            uint32_t a = sb + O_WHI + (kq * 16 + brow) * 144 + wid * 16;
            ldmB(bhf[kq], a);
            ldmB(blf[kq], a + (O_WLO - O_WHI));
        }
        for (int mt = 0; mt < mtiles; mt++) {
            unsigned ah[4][4], al[4][4];
            #pragma unroll
            for (int kq = 0; kq < 4; kq++) {
                uint32_t a = sb + O_GHI + (mt * 16 + arow) * 144 + kq * 32 + acol;
                ldmA(ah[kq], a);
                ldmA(al[kq], a + (O_GLO - O_GHI));
            }
            float dd[4] = {};
            #pragma unroll
            for (int kq = 0; kq < 4; kq++) {
                mmab(dd, ah[kq], bhf[kq]);
                mmab(dd, ah[kq], blf[kq]);
                mmab(dd, al[kq], bhf[kq]);
            }
            int c = 8 * wid + 2 * (lane & 3);
            #pragma unroll
            for (int h = 0; h < 2; h++) {
                int gr = mt * 16 + (lane >> 2) + 8 * h;
                if (gr < m) {
                    int rw = lrow[k * 128 + gr];
                    acc[rw * 72 + c]     += dd[2 * h];
                    acc[rw * 72 + c + 1] += dd[2 * h + 1];
                }
            }
        }
        __syncthreads();
    }
    // BN2 + SiLU -> split bf16 A3 tile (into gather region)
    const float* sc2 = (const float*)(sm + O_SC2);
    const float* tb2 = (const float*)(sm + O_TB2);
    #pragma unroll
    for (int i = 0; i < 16; i++) {
        int idx = t + 256 * i, r = idx >> 5, p = idx & 31;
        float x0 = acc[r * 72 + 2 * p] * sc2[2 * p] + tb2[2 * p];
        float x1 = acc[r * 72 + 2 * p + 1] * sc2[2 * p + 1] + tb2[2 * p + 1];
        x0 = silu(x0); x1 = silu(x1);
        unsigned hw, lw;
        split2(x0, x1, hw, lw);
        *(unsigned*)(sm + O_GHI + r * 144 + p * 4) = hw;
        *(unsigned*)(sm + O_GLO + r * 144 + p * 4) = lw;
    }
    __syncthreads();
    // W3 image into (dead) ACC region via cp.async (1088 16B-ops per array)
    for (int q = t; q < 2176; q += 256) {
        if (q < 1088) cpa16(sb + O_W3HI + q * 16, gW3hi + q * 8);
        else          cpa16(sb + O_W3LO + (q - 1088) * 16, gW3lo + (q - 1088) * 8);
    }
    CP_COMMIT();
    CP_WAIT0();
    __syncthreads();
    // cv3: warp = 16 rows x all 128 cols (per-n8 streaming epilogue)
    const float* sc3 = (const float*)(sm + O_SC3);
    const float* tb3 = (const float*)(sm + O_TB3);
    unsigned ah[4][4], al[4][4];
    #pragma unroll
    for (int kq = 0; kq < 4; kq++) {
        uint32_t a = sb + O_GHI + (wid * 16 + arow) * 144 + kq * 32 + acol;
        ldmA(ah[kq], a);
        ldmA(al[kq], a + (O_GLO - O_GHI));
    }
    #pragma unroll
    for (int half = 0; half < 2; half++)
        #pragma unroll
        for (int n8 = 0; n8 < 8; n8++) {
            unsigned b_h[4][2], b_l[4][2];
            #pragma unroll
            for (int kq = 0; kq < 4; kq++) {
                uint32_t a = sb + O_W3HI + (kq * 16 + brow) * 272 + half * 128 + n8 * 16;
                ldmB(b_h[kq], a);
                ldmB(b_l[kq], a + (O_W3LO - O_W3HI));
            }
            float dd[4] = {};
            #pragma unroll
            for (int kq = 0; kq < 4; kq++) {
                mmab(dd, ah[kq], b_h[kq]);
                mmab(dd, ah[kq], b_l[kq]);
                mmab(dd, al[kq], b_h[kq]);
            }
            int c = 64 * half + 8 * n8 + 2 * (lane & 3);
            float s0 = sc3[c], s1 = sc3[c + 1], t0 = tb3[c], t1 = tb3[c + 1];
            #pragma unroll
            for (int h = 0; h < 2; h++) {
                int site = base + wid * 16 + (lane >> 2) + 8 * h;
                if (site < NS) {
                    float2 f = *(const float2*)(feat + (size_t)site * 128 + c);
                    float o0 = silu(dd[2 * h] * s0 + t0 + f.x);
                    float o1 = silu(dd[2 * h + 1] * s1 + t1 + f.y);
                    *(float2*)(out + (size_t)site * 128 + c) = make_float2(o0, o1);
                }
            }
        }
}

// ============================================================================
extern "C" void kernel_launch(void* const* d_in, const int* in_sizes, int n_in,
                              void* d_out, int out_size) {
    const float* feat = (const float*)d_in[0];
    const int*   nbr  = (const int*)d_in[1];
    const float* W1 = (const float*)d_in[2];
    const float* W2 = (const float*)d_in[3];
    const float* W3 = (const float*)d_in[4];
    const float* g1 = (const float*)d_in[5];
    const float* b1 = (const float*)d_in[6];
    const float* m1 = (const float*)d_in[7];
    const float* v1 = (const float*)d_in[8];
    const float* g2 = (const float*)d_in[9];
    const float* b2 = (const float*)d_in[10];
    const float* m2 = (const float*)d_in[11];
    const float* v2 = (const float*)d_in[12];
    const float* g3 = (const float*)d_in[13];
    const float* b3 = (const float*)d_in[14];
    const float* m3 = (const float*)d_in[15];
    const float* v3 = (const float*)d_in[16];
    float* out = (float*)d_out;

    cudaFuncSetAttribute(k1, cudaFuncAttributeMaxDynamicSharedMemorySize, SM1);
    cudaFuncSetAttribute(k2, cudaFuncAttributeMaxDynamicSharedMemorySize, SM2);

    int grid = (NS + 127) / 128;   // 3907
    k0<<<232, 256>>>(W1, W2, W3);
    k1<<<grid, 256, SM1>>>(feat, g1, b1, m1, v1);
    k2<<<grid, 256, SM2>>>(feat, nbr, g2, b2, m2, v2, g3, b3, m3, v3, out);
}

// round 9
// speedup vs baseline: 2.1015x; 1.0237x over previous
#include <cuda_runtime.h>
#include <cuda_bf16.h>
#include <cstdint>

#define NS 500000
#define EPS 1e-5f

// split-bf16 hidden activations: 2 channels packed per u32, 32 u32 per site
__device__ __align__(16) unsigned g_hhi[NS * 32];
__device__ __align__(16) unsigned g_hlo[NS * 32];
// padded ldmatrix-ready weight images: [K][N+pad] u16, built by k0
__device__ __align__(16) unsigned short gW1hi[128 * 72], gW1lo[128 * 72];
__device__ __align__(16) unsigned short gW2hi[9 * 64 * 72], gW2lo[9 * 64 * 72];
__device__ __align__(16) unsigned short gW3hi[64 * 136], gW3lo[64 * 136];

__device__ __forceinline__ uint32_t s2u(const void* p) {
    uint32_t a;
    asm("{ .reg .u64 t; cvta.to.shared.u64 t, %1; cvt.u32.u64 %0, t; }" : "=r"(a) : "l"(p));
    return a;
}
__device__ __forceinline__ float silu(float x) { return x / (1.0f + __expf(-x)); }
// truncation split: hi = top 16 bits (exact), lo = rn(x - hi). 2 elements at once.
__device__ __forceinline__ void split2(float x0, float x1, unsigned& hi, unsigned& lo) {
    unsigned u0 = __float_as_uint(x0), u1 = __float_as_uint(x1);
    asm("prmt.b32 %0, %1, %2, 0x7632;" : "=r"(hi) : "r"(u0), "r"(u1));
    float l0 = x0 - __uint_as_float(u0 & 0xffff0000u);
    float l1 = x1 - __uint_as_float(u1 & 0xffff0000u);
    asm("cvt.rn.bf16x2.f32 %0, %1, %2;" : "=r"(lo) : "f"(l1), "f"(l0));
}
__device__ __forceinline__ void cpa16(uint32_t dst, const void* src) {
    asm volatile("cp.async.ca.shared.global [%0], [%1], 16;" :: "r"(dst), "l"(src));
}
#define CP_COMMIT() asm volatile("cp.async.commit_group;" ::: "memory")
#define CP_WAIT0()  asm volatile("cp.async.wait_group 0;" ::: "memory")
#define CP_WAIT1()  asm volatile("cp.async.wait_group 1;" ::: "memory")
__device__ __forceinline__ void ldmA(unsigned r[4], uint32_t a) {
    asm volatile("ldmatrix.sync.aligned.m8n8.x4.shared.b16 {%0,%1,%2,%3}, [%4];"
                 : "=r"(r[0]), "=r"(r[1]), "=r"(r[2]), "=r"(r[3]) : "r"(a));
}
__device__ __forceinline__ void ldmB(unsigned r[2], uint32_t a) {
    asm volatile("ldmatrix.sync.aligned.m8n8.x2.trans.shared.b16 {%0,%1}, [%2];"
                 : "=r"(r[0]), "=r"(r[1]) : "r"(a));
}
__device__ __forceinline__ void mmab(float d[4], const unsigned a[4], const unsigned b[2]) {
    asm volatile(
        "mma.sync.aligned.m16n8k16.row.col.f32.bf16.bf16.f32 "
        "{%0,%1,%2,%3},{%4,%5,%6,%7},{%8,%9},{%0,%1,%2,%3};"
        : "+f"(d[0]), "+f"(d[1]), "+f"(d[2]), "+f"(d[3])
        : "r"(a[0]), "r"(a[1]), "r"(a[2]), "r"(a[3]), "r"(b[0]), "r"(b[1]));
}

// ============================================================================
// k0: transpose + hi/lo-split + pad weights into ldmatrix B images [K][N+pad]
// ============================================================================
__global__ void k0(const float* __restrict__ W1, const float* __restrict__ W2,
                   const float* __restrict__ W3) {
    int i = blockIdx.x * 256 + threadIdx.x;
    float x;
    unsigned short *dh, *dl;
    int idx;
    if (i < 9216) {                       // W1: [128k][64n] -> [128][72]
        int k = i / 72, n = i % 72;
        x = (n < 64) ? W1[k * 64 + n] : 0.f;
        idx = i; dh = gW1hi; dl = gW1lo;
    } else if (i < 50688) {               // W2[kk]: [64k][64n] -> [9][64][72]
        int j = i - 9216;
        int kk = j / 4608, r = j % 4608, ki = r / 72, n = r % 72;
        x = (n < 64) ? W2[kk * 4096 + ki * 64 + n] : 0.f;
        idx = j; dh = gW2hi; dl = gW2lo;
    } else if (i < 59392) {               // W3: [64k][128n] -> [64][136]
        int j = i - 50688;
        int ki = j / 136, n = j % 136;
        x = (n < 128) ? W3[ki * 128 + n] : 0.f;
        idx = j; dh = gW3hi; dl = gW3lo;
    } else return;
    __nv_bfloat16 h = __float2bfloat16(x);
    dh[idx] = __bfloat16_as_ushort(h);
    dl[idx] = __bfloat16_as_ushort(__float2bfloat16(x - __bfloat162float(h)));
}

// ============================================================================
// k1: h = silu(bn1(feat @ W1))  [128 rows/block, 256 thr, warp = 16 rows]
// ============================================================================
#define O_B1HI 0
#define O_B1LO 18432
#define O_A1HI 36864
#define O_A1LO 47104
#define O_P1SC 57344
#define O_P1TB 57600
#define SM1    57856

__global__ __launch_bounds__(256, 3) void k1(
    const float* __restrict__ feat,
    const float* __restrict__ g1, const float* __restrict__ b1,
    const float* __restrict__ m1, const float* __restrict__ v1)
{
    extern __shared__ char sm[];
    uint32_t sb = s2u(sm);
    int t = threadIdx.x, wid = t >> 5, lane = t & 31;
    int base = blockIdx.x * 128;

    for (int q = t; q < 2304; q += 256) {
        if (q < 1152) cpa16(sb + O_B1HI + q * 16, gW1hi + q * 8);
        else          cpa16(sb + O_B1LO + (q - 1152) * 16, gW1lo + (q - 1152) * 8);
    }
    CP_COMMIT();
    if (t < 64) {
        float s = g1[t] * rsqrtf(v1[t] + EPS);
        ((float*)(sm + O_P1SC))[t] = s;
        ((float*)(sm + O_P1TB))[t] = b1[t] - m1[t] * s;
    }

    float d[8][4] = {};
    int arow = ((lane >> 3) & 1) * 8 + (lane & 7);
    int acol = (lane >> 4) * 16;
    int brow = arow;

    for (int kc = 0; kc < 4; kc++) {
        __syncthreads();
        #pragma unroll
        for (int i = 0; i < 4; i++) {
            int idx = t + 256 * i, r = idx >> 3, p = idx & 7;
            int site = base + r;
            float4 f = (site < NS) ? ((const float4*)feat)[(size_t)site * 32 + kc * 8 + p]
                                   : make_float4(0.f, 0.f, 0.f, 0.f);
            unsigned h0, l0, h1, l1;
            split2(f.x, f.y, h0, l0);
            split2(f.z, f.w, h1, l1);
            *(uint2*)(sm + O_A1HI + r * 80 + p * 8) = make_uint2(h0, h1);
            *(uint2*)(sm + O_A1LO + r * 80 + p * 8) = make_uint2(l0, l1);
        }
        CP_WAIT0();
        __syncthreads();
        unsigned ah[2][4], al[2][4];
        #pragma unroll
        for (int kq = 0; kq < 2; kq++) {
            uint32_t a = sb + O_A1HI + (wid * 16 + arow) * 80 + kq * 32 + acol;
            ldmA(ah[kq], a);
            ldmA(al[kq], a + (O_A1LO - O_A1HI));
        }
        #pragma unroll
        for (int n8 = 0; n8 < 8; n8++) {
            unsigned bh[2][2], bl[2][2];
            #pragma unroll
            for (int kq = 0; kq < 2; kq++) {
                uint32_t a = sb + O_B1HI + (kc * 32 + kq * 16 + brow) * 144 + n8 * 16;
                ldmB(bh[kq], a);
                ldmB(bl[kq], a + (O_B1LO - O_B1HI));
            }
            #pragma unroll
            for (int kq = 0; kq < 2; kq++) {
                mmab(d[n8], ah[kq], bh[kq]);
                mmab(d[n8], ah[kq], bl[kq]);
                mmab(d[n8], al[kq], bh[kq]);
            }
        }
    }
    const float* sc = (const float*)(sm + O_P1SC);
    const float* tb = (const float*)(sm + O_P1TB);
    #pragma unroll
    for (int n8 = 0; n8 < 8; n8++) {
        int c = 8 * n8 + 2 * (lane & 3);
        float s0 = sc[c], s1 = sc[c + 1], t0 = tb[c], t1 = tb[c + 1];
        #pragma unroll
        for (int h = 0; h < 2; h++) {
            int site = base + wid * 16 + (lane >> 2) + 8 * h;
            if (site < NS) {
                float o0 = silu(d[n8][2 * h] * s0 + t0);
                float o1 = silu(d[n8][2 * h + 1] * s1 + t1);
                unsigned hw, lw;
                split2(o0, o1, hw, lw);
                g_hhi[(size_t)site * 32 + (c >> 1)] = hw;
                g_hlo[(size_t)site * 32 + (c >> 1)] = lw;
            }
        }
    }
}

// ============================================================================
// k2: cv2 pipelined over <=18 work items (64-row chunks, double-buffered
//     gather + W2 slots, cp.async prefetch of item i+1 during compute of i),
//     then BN2/SiLU + cv3 (+BN3+residual+SiLU).
// ============================================================================
#define O_ACC  0           // f32 [128][66] = 33792
#define O_G0   33792       // gather slot 0: hi[64*144], lo[64*144]
#define O_G1   52224       // gather slot 1
#define O_W0   70656       // W2 slot 0: hi[9216], lo[9216]
#define O_W1   89088       // W2 slot 1
#define O_LP   107520      // u32 [9][128] packed (id<<8 | row)
#define O_CN   112128      // int [12]
#define O_IT   112176      // int [20] items (k<<1 | c0>>6)
#define O_NI   112256      // int
#define O_SC2  112288
#define O_TB2  112544
#define O_SC3  112800
#define O_TB3  113312
#define SM2    113856
#define O_A3HI 33792       // post-cv2: A3 tile reuses gather slots (128*144)
#define O_A3LO 52224
#define O_W3HI 70656       // W3 reuses W2 slots: u16 [64][136] = 17408
#define O_W3LO 88064

__global__ __launch_bounds__(256) void k2(
    const float* __restrict__ feat, const int* __restrict__ nbr,
    const float* __restrict__ g2, const float* __restrict__ b2,
    const float* __restrict__ m2, const float* __restrict__ v2,
    const float* __restrict__ g3, const float* __restrict__ b3,
    const float* __restrict__ m3, const float* __restrict__ v3,
    float* __restrict__ out)
{
    extern __shared__ char sm[];
    uint32_t sb = s2u(sm);
    int t = threadIdx.x, wid = t >> 5, lane = t & 31;
    int base = blockIdx.x * 128;
    unsigned* lp = (unsigned*)(sm + O_LP);
    int* cnt9 = (int*)(sm + O_CN);
    int* items = (int*)(sm + O_IT);
    float* acc = (float*)(sm + O_ACC);

    if (t < 64) {
        float s = g2[t] * rsqrtf(v2[t] + EPS);
        ((float*)(sm + O_SC2))[t] = s;
        ((float*)(sm + O_TB2))[t] = b2[t] - m2[t] * s;
    }
    if (t < 128) {
        float s = g3[t] * rsqrtf(v3[t] + EPS);
        ((float*)(sm + O_SC3))[t] = s;
        ((float*)(sm + O_TB3))[t] = b3[t] - m3[t] * s;
    }
    #pragma unroll
    for (int i = 0; i < 33; i++) acc[t + 256 * i] = 0.f;

    // compaction: warp w handles offsets w, w+8
    for (int k = wid; k < 9; k += 8) {
        int cbase = 0;
        #pragma unroll
        for (int g = 0; g < 4; g++) {
            int site = base + g * 32 + lane;
            int id = (site < NS) ? __ldg(&nbr[(size_t)k * NS + site]) : NS;
            bool val = id < NS;
            unsigned msk = __ballot_sync(0xffffffffu, val);
            if (val) {
                int p = cbase + __popc(msk & ((1u << lane) - 1u));
                lp[k * 128 + p] = ((unsigned)id << 8) | (g * 32 + lane);
            }
            cbase += __popc(msk);
        }
        if (lane == 0) cnt9[k] = cbase;
    }
    __syncthreads();
    if (t == 0) {   // build item list: 64-row chunks
        int ni = 0;
        for (int k = 0; k < 9; k++)
            for (int c0 = 0; c0 < cnt9[k]; c0 += 64)
                items[ni++] = (k << 1) | (c0 >> 6);
        *(int*)(sm + O_NI) = ni;
    }
    __syncthreads();
    int nitems = *(int*)(sm + O_NI);

    auto issue_item = [&](int j) {
        int pk = items[j];
        int kk = pk >> 1, c0 = (pk & 1) << 6;
        int chunk = min(cnt9[kk] - c0, 64);
        uint32_t gb = sb + ((j & 1) ? O_G1 : O_G0);
        for (int q = t; q < chunk * 16; q += 256) {
            int r = q >> 4, s = q & 15;
            unsigned id = lp[kk * 128 + c0 + r] >> 8;
            if (s < 8) cpa16(gb + r * 144 + s * 16, g_hhi + (size_t)id * 32 + s * 4);
            else       cpa16(gb + 9216 + r * 144 + (s - 8) * 16, g_hlo + (size_t)id * 32 + (s - 8) * 4);
        }
        uint32_t wbuf = sb + ((j & 1) ? O_W1 : O_W0);
        for (int q = t; q < 1152; q += 256) {
            if (q < 576) cpa16(wbuf + q * 16, gW2hi + kk * 4608 + q * 8);
            else         cpa16(wbuf + 9216 + (q - 576) * 16, gW2lo + kk * 4608 + (q - 576) * 8);
        }
    };

    int arow = ((lane >> 3) & 1) * 8 + (lane & 7);
    int acol = (lane >> 4) * 16;
    int brow = arow;

    // prologue: prefetch item 0
    issue_item(0);
    CP_COMMIT();

    for (int it = 0; it < nitems; it++) {
        __syncthreads();   // prior compute done -> safe to overwrite other slot
        if (it + 1 < nitems) issue_item(it + 1);
        CP_COMMIT();
        if (it + 1 < nitems) CP_WAIT1(); else CP_WAIT0();
        __syncthreads();

        int pk = items[it];
        int kk = pk >> 1, c0 = (pk & 1) << 6;
        int chunk = min(cnt9[kk] - c0, 64);
        uint32_t gb = sb + ((it & 1) ? O_G1 : O_G0);
        uint32_t wbuf = sb + ((it & 1) ? O_W1 : O_W0);
        int mtiles = (chunk + 15) >> 4;

        unsigned bhf[4][2], blf[4][2];
        #pragma unroll
        for (int kq = 0; kq < 4; kq++) {
            uint32_t a = wbuf + (kq * 16 + brow) * 144 + wid * 16;
            ldmB(bhf[kq], a);
            ldmB(blf[kq], a + 9216);
        }
        for (int mt = 0; mt < mtiles; mt++) {
            unsigned ah[4][4], al[4][4];
            #pragma unroll
            for (int kq = 0; kq < 4; kq++) {
                uint32_t a = gb + (mt * 16 + arow) * 144 + kq * 32 + acol;
                ldmA(ah[kq], a);
                ldmA(al[kq], a + 9216);
            }
            float dd[4] = {};
            #pragma unroll
            for (int kq = 0; kq < 4; kq++) {
                mmab(dd, ah[kq], bhf[kq]);
                mmab(dd, ah[kq], blf[kq]);
                mmab(dd, al[kq], bhf[kq]);
            }
            int c = 8 * wid + 2 * (lane & 3);
            #pragma unroll
            for (int h = 0; h < 2; h++) {
                int gr = mt * 16 + (lane >> 2) + 8 * h;
                if (gr < chunk) {
                    int rw = lp[kk * 128 + c0 + gr] & 255;
                    acc[rw * 66 + c]     += dd[2 * h];
                    acc[rw * 66 + c + 1] += dd[2 * h + 1];
                }
            }
        }
    }
    __syncthreads();
    // BN2 + SiLU -> split bf16 A3 tile (reuses gather slots)
    const float* sc2 = (const float*)(sm + O_SC2);
    const float* tb2 = (const float*)(sm + O_TB2);
    #pragma unroll
    for (int i = 0; i < 16; i++) {
        int idx = t + 256 * i, r = idx >> 5, p = idx & 31;
        float x0 = acc[r * 66 + 2 * p] * sc2[2 * p] + tb2[2 * p];
        float x1 = acc[r * 66 + 2 * p + 1] * sc2[2 * p + 1] + tb2[2 * p + 1];
        x0 = silu(x0); x1 = silu(x1);
        unsigned hw, lw;
        split2(x0, x1, hw, lw);
        *(unsigned*)(sm + O_A3HI + r * 144 + p * 4) = hw;
        *(unsigned*)(sm + O_A3LO + r * 144 + p * 4) = lw;
    }
    // W3 image into (dead) W2 slots
    for (int q = t; q < 2176; q += 256) {
        if (q < 1088) cpa16(sb + O_W3HI + q * 16, gW3hi + q * 8);
        else          cpa16(sb + O_W3LO + (q - 1088) * 16, gW3lo + (q - 1088) * 8);
    }
    CP_COMMIT();
    CP_WAIT0();
    __syncthreads();
    // cv3: warp = 16 rows x all 128 cols
    const float* sc3 = (const float*)(sm + O_SC3);
    const float* tb3 = (const float*)(sm + O_TB3);
    unsigned ah[4][4], al[4][4];
    #pragma unroll
    for (int kq = 0; kq < 4; kq++) {
        uint32_t a = sb + O_A3HI + (wid * 16 + arow) * 144 + kq * 32 + acol;
        ldmA(ah[kq], a);
        ldmA(al[kq], a + (O_A3LO - O_A3HI));
    }
    #pragma unroll
    for (int half = 0; half < 2; half++)
        #pragma unroll
        for (int n8 = 0; n8 < 8; n8++) {
            unsigned b_h[4][2], b_l[4][2];
            #pragma unroll
            for (int kq = 0; kq < 4; kq++) {
                uint32_t a = sb + O_W3HI + (kq * 16 + brow) * 272 + half * 128 + n8 * 16;
                ldmB(b_h[kq], a);
                ldmB(b_l[kq], a + (O_W3LO - O_W3HI));
            }
            float dd[4] = {};
            #pragma unroll
            for (int kq = 0; kq < 4; kq++) {
                mmab(dd, ah[kq], b_h[kq]);
                mmab(dd, ah[kq], b_l[kq]);
                mmab(dd, al[kq], b_h[kq]);
            }
            int c = 64 * half + 8 * n8 + 2 * (lane & 3);
            float s0 = sc3[c], s1 = sc3[c + 1], t0 = tb3[c], t1 = tb3[c + 1];
            #pragma unroll
            for (int h = 0; h < 2; h++) {
                int site = base + wid * 16 + (lane >> 2) + 8 * h;
                if (site < NS) {
                    float2 f = *(const float2*)(feat + (size_t)site * 128 + c);
                    float o0 = silu(dd[2 * h] * s0 + t0 + f.x);
                    float o1 = silu(dd[2 * h + 1] * s1 + t1 + f.y);
                    *(float2*)(out + (size_t)site * 128 + c) = make_float2(o0, o1);
                }
            }
        }
}

// ============================================================================
extern "C" void kernel_launch(void* const* d_in, const int* in_sizes, int n_in,
                              void* d_out, int out_size) {
    const float* feat = (const float*)d_in[0];
    const int*   nbr  = (const int*)d_in[1];
    const float* W1 = (const float*)d_in[2];
    const float* W2 = (const float*)d_in[3];
    const float* W3 = (const float*)d_in[4];
    const float* g1 = (const float*)d_in[5];
    const float* b1 = (const float*)d_in[6];
    const float* m1 = (const float*)d_in[7];
    const float* v1 = (const float*)d_in[8];
    const float* g2 = (const float*)d_in[9];
    const float* b2 = (const float*)d_in[10];
    const float* m2 = (const float*)d_in[11];
    const float* v2 = (const float*)d_in[12];
    const float* g3 = (const float*)d_in[13];
    const float* b3 = (const float*)d_in[14];
    const float* m3 = (const float*)d_in[15];
    const float* v3 = (const float*)d_in[16];
    float* out = (float*)d_out;

    cudaFuncSetAttribute(k1, cudaFuncAttributeMaxDynamicSharedMemorySize, SM1);
    cudaFuncSetAttribute(k2, cudaFuncAttributeMaxDynamicSharedMemorySize, SM2);

    int grid = (NS + 127) / 128;   // 3907
    k0<<<232, 256>>>(W1, W2, W3);
    k1<<<grid, 256, SM1>>>(feat, g1, b1, m1, v1);
    k2<<<grid, 256, SM2>>>(feat, nbr, g2, b2, m2, v2, g3, b3, m3, v3, out);
}